// round 1
// baseline (speedup 1.0000x reference)
#include <cuda_runtime.h>
#include <math.h>

#define N_NODES 20000
#define N_EDGES 5000
#define D       128
#define ATT     32
#define ECAP    384     // max nodes per edge (mean 200, sigma ~14 -> 13 sigma)
#define NCAP    128     // max edges per node (mean 50,  sigma ~7  -> 11 sigma)
#define LN_EPS  1e-5f
#define DEG_EPS 1e-12f

// ---------------- device scratch (no allocations allowed) ----------------
__device__ int   g_edge_cnt[N_EDGES];
__device__ int   g_node_cnt[N_NODES];
__device__ int   g_edge_nodes[N_EDGES * ECAP];   // 7.7 MB
__device__ int   g_node_edges[N_NODES * NCAP];   // 10.2 MB
__device__ float g_de_inv[N_EDGES];
__device__ float g_dv_inv[N_NODES];
__device__ float g_x[N_NODES * D];               // 10.2 MB
__device__ float g_edge[N_EDGES * D];            // 2.6 MB
__device__ float g_logits[N_EDGES];
__device__ float g_scores[N_EDGES];

// ---------------- init: copy x0 -> x, zero counters ----------------
__global__ void init_kernel(const float* __restrict__ x0) {
    int i = blockIdx.x * blockDim.x + threadIdx.x;
    int stride = gridDim.x * blockDim.x;
    for (int k = i; k < N_NODES * D; k += stride) g_x[k] = x0[k];
    for (int k = i; k < N_EDGES; k += stride) g_edge_cnt[k] = 0;
    for (int k = i; k < N_NODES; k += stride) g_node_cnt[k] = 0;
}

// ---------------- single pass over dense H: build adjacency ----------------
// H is [N, E] row-major; E = 5000 is divisible by 4, rows are 16B aligned,
// so a float4 never crosses a row boundary.
__global__ void build_kernel(const float* __restrict__ H) {
    const long long total4 = (long long)N_NODES * N_EDGES / 4;
    long long idx = (long long)blockIdx.x * blockDim.x + threadIdx.x;
    long long stride = (long long)gridDim.x * blockDim.x;
    const float4* H4 = (const float4*)H;
    for (long long q = idx; q < total4; q += stride) {
        float4 v = __ldg(&H4[q]);
        long long l = q * 4;
        int n = (int)(l / N_EDGES);
        int e = (int)(l % N_EDGES);
        float vals[4] = {v.x, v.y, v.z, v.w};
        #pragma unroll
        for (int c = 0; c < 4; c++) {
            if (vals[c] != 0.0f) {
                int ee = e + c;
                int pe = atomicAdd(&g_edge_cnt[ee], 1);
                if (pe < ECAP) g_edge_nodes[ee * ECAP + pe] = n;
                int pn = atomicAdd(&g_node_cnt[n], 1);
                if (pn < NCAP) g_node_edges[n * NCAP + pn] = ee;
            }
        }
    }
}

// ---------------- degree inverses ----------------
__global__ void inv_kernel() {
    int i = blockIdx.x * blockDim.x + threadIdx.x;
    if (i < N_EDGES) g_de_inv[i] = 1.0f / fmaxf((float)g_edge_cnt[i], DEG_EPS);
    if (i < N_NODES) g_dv_inv[i] = 1.0f / fmaxf((float)g_node_cnt[i], DEG_EPS);
}

// ---------------- V -> E mean: edge[e] = de_inv[e] * sum_{n in e} x[n] ----------------
// One block per edge, 128 threads (one per feature dim).
__global__ void v2e_kernel() {
    int e = blockIdx.x;
    int d = threadIdx.x;
    __shared__ int sh[128];
    int deg = min(g_edge_cnt[e], ECAP);
    const int* lst = &g_edge_nodes[e * ECAP];
    float acc = 0.0f;
    for (int base = 0; base < deg; base += 128) {
        int m = min(128, deg - base);
        __syncthreads();
        if (d < m) sh[d] = lst[base + d];
        __syncthreads();
        int j = 0;
        #pragma unroll 2
        for (; j + 4 <= m; j += 4) {
            float a0 = g_x[(size_t)sh[j + 0] * D + d];
            float a1 = g_x[(size_t)sh[j + 1] * D + d];
            float a2 = g_x[(size_t)sh[j + 2] * D + d];
            float a3 = g_x[(size_t)sh[j + 3] * D + d];
            acc += (a0 + a1) + (a2 + a3);
        }
        for (; j < m; j++) acc += g_x[(size_t)sh[j] * D + d];
    }
    g_edge[e * D + d] = acc * g_de_inv[e];
}

// ---------------- E -> V mean + residual + LayerNorm (fused) ----------------
// One block per node, 128 threads (one per dim).
__global__ void e2v_ln_kernel(const float* __restrict__ x0,
                              const float* __restrict__ gamma,
                              const float* __restrict__ beta) {
    int n = blockIdx.x;
    int d = threadIdx.x;
    __shared__ int   sh[NCAP];
    __shared__ float red[4];
    int deg = min(g_node_cnt[n], NCAP);
    const int* lst = &g_node_edges[n * NCAP];
    if (d < deg) sh[d] = lst[d];   // NCAP == blockDim == 128
    __syncthreads();
    float acc = 0.0f;
    int j = 0;
    #pragma unroll 2
    for (; j + 4 <= deg; j += 4) {
        float a0 = g_edge[sh[j + 0] * D + d];
        float a1 = g_edge[sh[j + 1] * D + d];
        float a2 = g_edge[sh[j + 2] * D + d];
        float a3 = g_edge[sh[j + 3] * D + d];
        acc += (a0 + a1) + (a2 + a3);
    }
    for (; j < deg; j++) acc += g_edge[sh[j] * D + d];

    float y = acc * g_dv_inv[n] + x0[n * D + d];

    // block mean over 128 dims
    float s = y;
    #pragma unroll
    for (int o = 16; o > 0; o >>= 1) s += __shfl_xor_sync(0xffffffffu, s, o);
    if ((d & 31) == 0) red[d >> 5] = s;
    __syncthreads();
    float mu = (red[0] + red[1] + red[2] + red[3]) * (1.0f / D);
    float dy = y - mu;
    __syncthreads();
    float s2 = dy * dy;
    #pragma unroll
    for (int o = 16; o > 0; o >>= 1) s2 += __shfl_xor_sync(0xffffffffu, s2, o);
    if ((d & 31) == 0) red[d >> 5] = s2;
    __syncthreads();
    float var = (red[0] + red[1] + red[2] + red[3]) * (1.0f / D);
    g_x[n * D + d] = dy * rsqrtf(var + LN_EPS) * gamma[d] + beta[d];
}

// ---------------- attention logits: one warp per edge ----------------
__global__ void logits_kernel(const float* __restrict__ W,
                              const float* __restrict__ b,
                              const float* __restrict__ q) {
    int e = blockIdx.x * (blockDim.x >> 5) + (threadIdx.x >> 5);
    int j = threadIdx.x & 31;
    if (e >= N_EDGES) return;
    const float* eo = &g_edge[e * D];
    float acc = 0.0f;
    #pragma unroll 4
    for (int dd = 0; dd < D; dd++) acc += eo[dd] * W[dd * ATT + j];
    float t = tanhf(acc + b[j]) * q[j];
    #pragma unroll
    for (int o = 16; o > 0; o >>= 1) t += __shfl_xor_sync(0xffffffffu, t, o);
    if (j == 0) g_logits[e] = t;
}

// ---------------- softmax over E (single block) ----------------
__global__ void softmax_kernel() {
    __shared__ float red[32];
    int t = threadIdx.x;
    // max
    float m = -1e30f;
    for (int e = t; e < N_EDGES; e += blockDim.x) m = fmaxf(m, g_logits[e]);
    #pragma unroll
    for (int o = 16; o > 0; o >>= 1) m = fmaxf(m, __shfl_xor_sync(0xffffffffu, m, o));
    if ((t & 31) == 0) red[t >> 5] = m;
    __syncthreads();
    if (t < 32) {
        float v = red[t];
        #pragma unroll
        for (int o = 16; o > 0; o >>= 1) v = fmaxf(v, __shfl_xor_sync(0xffffffffu, v, o));
        if (t == 0) red[0] = v;
    }
    __syncthreads();
    float mx = red[0];
    __syncthreads();
    // sum of exp
    float s = 0.0f;
    for (int e = t; e < N_EDGES; e += blockDim.x) s += expf(g_logits[e] - mx);
    #pragma unroll
    for (int o = 16; o > 0; o >>= 1) s += __shfl_xor_sync(0xffffffffu, s, o);
    if ((t & 31) == 0) red[t >> 5] = s;
    __syncthreads();
    if (t < 32) {
        float v = red[t];
        #pragma unroll
        for (int o = 16; o > 0; o >>= 1) v += __shfl_xor_sync(0xffffffffu, v, o);
        if (t == 0) red[0] = v;
    }
    __syncthreads();
    float inv = 1.0f / red[0];
    for (int e = t; e < N_EDGES; e += blockDim.x)
        g_scores[e] = expf(g_logits[e] - mx) * inv;
}

// ---------------- pooled output: out[d] = sum_e scores[e] * edge[e][d] ----------------
__global__ void pool_kernel(float* __restrict__ out) {
    int d = blockIdx.x;
    int t = threadIdx.x;
    float acc = 0.0f;
    for (int e = t; e < N_EDGES; e += blockDim.x)
        acc += g_scores[e] * g_edge[e * D + d];
    __shared__ float red[8];
    #pragma unroll
    for (int o = 16; o > 0; o >>= 1) acc += __shfl_xor_sync(0xffffffffu, acc, o);
    if ((t & 31) == 0) red[t >> 5] = acc;
    __syncthreads();
    if (t == 0) {
        float s = 0.0f;
        for (int w = 0; w < (blockDim.x >> 5); w++) s += red[w];
        out[d] = s;
    }
}

// ---------------- launch ----------------
extern "C" void kernel_launch(void* const* d_in, const int* in_sizes, int n_in,
                              void* d_out, int out_size) {
    const float* x0    = (const float*)d_in[0];   // node_embeddings [N, D]
    const float* H     = (const float*)d_in[1];   // hypergraph_matrix [N, E]
    const float* gamma = (const float*)d_in[2];   // ln_gamma [D]
    const float* beta  = (const float*)d_in[3];   // ln_beta [D]
    const float* W     = (const float*)d_in[4];   // W_att [D, ATT]
    const float* b     = (const float*)d_in[5];   // b_att [ATT]
    const float* q     = (const float*)d_in[6];   // q_att [ATT]
    float* out = (float*)d_out;

    init_kernel<<<2048, 256>>>(x0);
    build_kernel<<<4096, 256>>>(H);
    inv_kernel<<<(N_NODES + 255) / 256, 256>>>();

    for (int l = 0; l < 4; l++) {
        v2e_kernel<<<N_EDGES, 128>>>();
        e2v_ln_kernel<<<N_NODES, 128>>>(x0, gamma, beta);
    }
    // final per-edge masked mean == edge mean on final x (counts are identical)
    v2e_kernel<<<N_EDGES, 128>>>();

    logits_kernel<<<(N_EDGES + 3) / 4, 128>>>(W, b, q);
    softmax_kernel<<<1, 1024>>>();
    pool_kernel<<<D, 256>>>(out);
}

// round 2
// speedup vs baseline: 1.2183x; 1.2183x over previous
#include <cuda_runtime.h>
#include <math.h>

#define N_NODES 20000
#define N_EDGES 5000
#define D       128
#define ATT     32
#define ECAP    384     // max nodes per edge (mean 200, sigma ~14 -> 13 sigma)
#define NCAP    128     // max edges per node (mean 50,  sigma ~7  -> 11 sigma)
#define LN_EPS  1e-5f
#define DEG_EPS 1e-12f
#define FULL    0xffffffffu

// ---------------- device scratch (no allocations allowed) ----------------
__device__ int   g_edge_cnt[N_EDGES];
__device__ int   g_node_cnt[N_NODES];
__device__ int   g_edge_nodes[N_EDGES * ECAP];   // 7.7 MB
__device__ int   g_node_edges[N_NODES * NCAP];   // 10.2 MB
__device__ float g_de_inv[N_EDGES];
__device__ float g_dv_inv[N_NODES];
__device__ float4 g_x[N_NODES * 32];             // 10.2 MB  (row = 32 float4)
__device__ float4 g_edge[N_EDGES * 32];          // 2.6 MB
__device__ float g_logits[N_EDGES];
__device__ float g_scores[N_EDGES];

// ---------------- init: copy x0 -> x, zero counters ----------------
__global__ void init_kernel(const float4* __restrict__ x0) {
    int i = blockIdx.x * blockDim.x + threadIdx.x;
    int stride = gridDim.x * blockDim.x;
    for (int k = i; k < N_NODES * 32; k += stride) g_x[k] = x0[k];
    for (int k = i; k < N_EDGES; k += stride) g_edge_cnt[k] = 0;
    for (int k = i; k < N_NODES; k += stride) g_node_cnt[k] = 0;
}

// ---------------- single pass over dense H: build adjacency ----------------
__global__ void build_kernel(const float* __restrict__ H) {
    const long long total4 = (long long)N_NODES * N_EDGES / 4;
    long long idx = (long long)blockIdx.x * blockDim.x + threadIdx.x;
    long long stride = (long long)gridDim.x * blockDim.x;
    const float4* H4 = (const float4*)H;
    for (long long q = idx; q < total4; q += stride) {
        float4 v = __ldg(&H4[q]);
        long long l = q * 4;
        int n = (int)(l / N_EDGES);
        int e = (int)(l % N_EDGES);
        float vals[4] = {v.x, v.y, v.z, v.w};
        #pragma unroll
        for (int c = 0; c < 4; c++) {
            if (vals[c] != 0.0f) {
                int ee = e + c;
                int pe = atomicAdd(&g_edge_cnt[ee], 1);
                if (pe < ECAP) g_edge_nodes[ee * ECAP + pe] = n;
                int pn = atomicAdd(&g_node_cnt[n], 1);
                if (pn < NCAP) g_node_edges[n * NCAP + pn] = ee;
            }
        }
    }
}

// ---------------- degree inverses ----------------
__global__ void inv_kernel() {
    int i = blockIdx.x * blockDim.x + threadIdx.x;
    if (i < N_EDGES) g_de_inv[i] = 1.0f / fmaxf((float)g_edge_cnt[i], DEG_EPS);
    if (i < N_NODES) g_dv_inv[i] = 1.0f / fmaxf((float)g_node_cnt[i], DEG_EPS);
}

// ---------------- V -> E mean: one WARP per edge, float4 lanes ----------------
__global__ void v2e_kernel() {
    int e = (blockIdx.x * blockDim.x + threadIdx.x) >> 5;   // exactly N_EDGES warps
    int lane = threadIdx.x & 31;
    int deg = min(g_edge_cnt[e], ECAP);
    const int* lst = &g_edge_nodes[e * ECAP];
    float4 acc = make_float4(0.f, 0.f, 0.f, 0.f);
    for (int base = 0; base < deg; base += 32) {
        int m = min(32, deg - base);
        int idx = (lane < m) ? lst[base + lane] : 0;
        int k = 0;
        for (; k + 4 <= m; k += 4) {
            int n0 = __shfl_sync(FULL, idx, k);
            int n1 = __shfl_sync(FULL, idx, k + 1);
            int n2 = __shfl_sync(FULL, idx, k + 2);
            int n3 = __shfl_sync(FULL, idx, k + 3);
            float4 a0 = g_x[n0 * 32 + lane];
            float4 a1 = g_x[n1 * 32 + lane];
            float4 a2 = g_x[n2 * 32 + lane];
            float4 a3 = g_x[n3 * 32 + lane];
            acc.x += (a0.x + a1.x) + (a2.x + a3.x);
            acc.y += (a0.y + a1.y) + (a2.y + a3.y);
            acc.z += (a0.z + a1.z) + (a2.z + a3.z);
            acc.w += (a0.w + a1.w) + (a2.w + a3.w);
        }
        for (; k < m; k++) {
            int n0 = __shfl_sync(FULL, idx, k);
            float4 a0 = g_x[n0 * 32 + lane];
            acc.x += a0.x; acc.y += a0.y; acc.z += a0.z; acc.w += a0.w;
        }
    }
    float s = g_de_inv[e];
    acc.x *= s; acc.y *= s; acc.z *= s; acc.w *= s;
    g_edge[e * 32 + lane] = acc;
}

// ---------------- E -> V mean + residual + LayerNorm: one WARP per node ----------------
__global__ void e2v_ln_kernel(const float4* __restrict__ x0,
                              const float4* __restrict__ gamma,
                              const float4* __restrict__ beta) {
    int n = (blockIdx.x * blockDim.x + threadIdx.x) >> 5;   // exactly N_NODES warps
    int lane = threadIdx.x & 31;
    int deg = min(g_node_cnt[n], NCAP);
    const int* lst = &g_node_edges[n * NCAP];
    float4 acc = make_float4(0.f, 0.f, 0.f, 0.f);
    for (int base = 0; base < deg; base += 32) {
        int m = min(32, deg - base);
        int idx = (lane < m) ? lst[base + lane] : 0;
        int k = 0;
        for (; k + 4 <= m; k += 4) {
            int e0 = __shfl_sync(FULL, idx, k);
            int e1 = __shfl_sync(FULL, idx, k + 1);
            int e2 = __shfl_sync(FULL, idx, k + 2);
            int e3 = __shfl_sync(FULL, idx, k + 3);
            float4 a0 = g_edge[e0 * 32 + lane];
            float4 a1 = g_edge[e1 * 32 + lane];
            float4 a2 = g_edge[e2 * 32 + lane];
            float4 a3 = g_edge[e3 * 32 + lane];
            acc.x += (a0.x + a1.x) + (a2.x + a3.x);
            acc.y += (a0.y + a1.y) + (a2.y + a3.y);
            acc.z += (a0.z + a1.z) + (a2.z + a3.z);
            acc.w += (a0.w + a1.w) + (a2.w + a3.w);
        }
        for (; k < m; k++) {
            int e0 = __shfl_sync(FULL, idx, k);
            float4 a0 = g_edge[e0 * 32 + lane];
            acc.x += a0.x; acc.y += a0.y; acc.z += a0.z; acc.w += a0.w;
        }
    }
    float s = g_dv_inv[n];
    float4 r = x0[n * 32 + lane];
    float4 y;
    y.x = acc.x * s + r.x;
    y.y = acc.y * s + r.y;
    y.z = acc.z * s + r.z;
    y.w = acc.w * s + r.w;

    // mean over 128 dims (4 per lane)
    float sm = (y.x + y.y) + (y.z + y.w);
    #pragma unroll
    for (int o = 16; o > 0; o >>= 1) sm += __shfl_xor_sync(FULL, sm, o);
    float mu = sm * (1.0f / D);
    float4 dy;
    dy.x = y.x - mu; dy.y = y.y - mu; dy.z = y.z - mu; dy.w = y.w - mu;
    float s2 = (dy.x * dy.x + dy.y * dy.y) + (dy.z * dy.z + dy.w * dy.w);
    #pragma unroll
    for (int o = 16; o > 0; o >>= 1) s2 += __shfl_xor_sync(FULL, s2, o);
    float rstd = rsqrtf(s2 * (1.0f / D) + LN_EPS);
    float4 g = gamma[lane];
    float4 bb = beta[lane];
    float4 o4;
    o4.x = dy.x * rstd * g.x + bb.x;
    o4.y = dy.y * rstd * g.y + bb.y;
    o4.z = dy.z * rstd * g.z + bb.z;
    o4.w = dy.w * rstd * g.w + bb.w;
    g_x[n * 32 + lane] = o4;
}

// ---------------- attention logits: one warp per edge ----------------
__global__ void logits_kernel(const float* __restrict__ W,
                              const float* __restrict__ b,
                              const float* __restrict__ q) {
    int e = (blockIdx.x * blockDim.x + threadIdx.x) >> 5;
    int j = threadIdx.x & 31;
    if (e >= N_EDGES) return;
    const float* eo = (const float*)&g_edge[e * 32];
    float acc = 0.0f;
    #pragma unroll 4
    for (int dd = 0; dd < D; dd++) acc += eo[dd] * W[dd * ATT + j];
    float t = tanhf(acc + b[j]) * q[j];
    #pragma unroll
    for (int o = 16; o > 0; o >>= 1) t += __shfl_xor_sync(FULL, t, o);
    if (j == 0) g_logits[e] = t;
}

// ---------------- softmax over E (single block) ----------------
__global__ void softmax_kernel() {
    __shared__ float red[32];
    int t = threadIdx.x;
    float m = -1e30f;
    for (int e = t; e < N_EDGES; e += blockDim.x) m = fmaxf(m, g_logits[e]);
    #pragma unroll
    for (int o = 16; o > 0; o >>= 1) m = fmaxf(m, __shfl_xor_sync(FULL, m, o));
    if ((t & 31) == 0) red[t >> 5] = m;
    __syncthreads();
    if (t < 32) {
        float v = red[t];
        #pragma unroll
        for (int o = 16; o > 0; o >>= 1) v = fmaxf(v, __shfl_xor_sync(FULL, v, o));
        if (t == 0) red[0] = v;
    }
    __syncthreads();
    float mx = red[0];
    __syncthreads();
    float s = 0.0f;
    for (int e = t; e < N_EDGES; e += blockDim.x) s += expf(g_logits[e] - mx);
    #pragma unroll
    for (int o = 16; o > 0; o >>= 1) s += __shfl_xor_sync(FULL, s, o);
    if ((t & 31) == 0) red[t >> 5] = s;
    __syncthreads();
    if (t < 32) {
        float v = red[t];
        #pragma unroll
        for (int o = 16; o > 0; o >>= 1) v += __shfl_xor_sync(FULL, v, o);
        if (t == 0) red[0] = v;
    }
    __syncthreads();
    float inv = 1.0f / red[0];
    for (int e = t; e < N_EDGES; e += blockDim.x)
        g_scores[e] = expf(g_logits[e] - mx) * inv;
}

// ---------------- pooled output: out[d] = sum_e scores[e] * edge[e][d] ----------------
__global__ void pool_kernel(float* __restrict__ out) {
    int d = blockIdx.x;
    int t = threadIdx.x;
    const float* eo = (const float*)g_edge;
    float acc = 0.0f;
    for (int e = t; e < N_EDGES; e += blockDim.x)
        acc += g_scores[e] * eo[e * D + d];
    __shared__ float red[8];
    #pragma unroll
    for (int o = 16; o > 0; o >>= 1) acc += __shfl_xor_sync(FULL, acc, o);
    if ((t & 31) == 0) red[t >> 5] = acc;
    __syncthreads();
    if (t == 0) {
        float s = 0.0f;
        for (int w = 0; w < (blockDim.x >> 5); w++) s += red[w];
        out[d] = s;
    }
}

// ---------------- launch ----------------
extern "C" void kernel_launch(void* const* d_in, const int* in_sizes, int n_in,
                              void* d_out, int out_size) {
    const float* x0    = (const float*)d_in[0];   // node_embeddings [N, D]
    const float* H     = (const float*)d_in[1];   // hypergraph_matrix [N, E]
    const float* gamma = (const float*)d_in[2];   // ln_gamma [D]
    const float* beta  = (const float*)d_in[3];   // ln_beta [D]
    const float* W     = (const float*)d_in[4];   // W_att [D, ATT]
    const float* b     = (const float*)d_in[5];   // b_att [ATT]
    const float* q     = (const float*)d_in[6];   // q_att [ATT]
    float* out = (float*)d_out;

    init_kernel<<<2048, 256>>>((const float4*)x0);
    build_kernel<<<4096, 256>>>(H);
    inv_kernel<<<(N_NODES + 255) / 256, 256>>>();

    for (int l = 0; l < 4; l++) {
        v2e_kernel<<<N_EDGES / 8, 256>>>();                       // 1 warp / edge
        e2v_ln_kernel<<<N_NODES / 8, 256>>>((const float4*)x0,
                                            (const float4*)gamma,
                                            (const float4*)beta); // 1 warp / node
    }
    // final per-edge masked mean == edge mean on final x (counts are identical)
    v2e_kernel<<<N_EDGES / 8, 256>>>();

    logits_kernel<<<(N_EDGES + 7) / 8, 256>>>(W, b, q);
    softmax_kernel<<<1, 1024>>>();
    pool_kernel<<<D, 256>>>(out);
}

// round 3
// speedup vs baseline: 1.4547x; 1.1940x over previous
#include <cuda_runtime.h>
#include <cuda_fp16.h>
#include <math.h>

#define N_NODES 20000
#define N_EDGES 5000
#define D       128
#define ATT     32
#define ECAP    384     // max nodes per edge (mean 200, sigma ~14)
#define NCAP    128     // max edges per node (mean 50,  sigma ~7)
#define LN_EPS  1e-5f
#define DEG_EPS 1e-12f
#define FULL    0xffffffffu

// ---------------- device scratch (no allocations allowed) ----------------
__device__ int   g_edge_cnt[N_EDGES];
__device__ int   g_node_cnt[N_NODES];
__device__ int   g_edge_nodes[N_EDGES * ECAP];   // 7.7 MB
__device__ int   g_node_edges[N_NODES * NCAP];   // 10.2 MB
__device__ float g_de_inv[N_EDGES];
__device__ float g_dv_inv[N_NODES];
__device__ uint2  g_x[N_NODES * 32];             // fp16 features: row = 32 lanes x 4 halves (256B)
__device__ uint2  g_edge_h[N_EDGES * 32];        // fp16 edge means
__device__ float4 g_edge_out[N_EDGES * 32];      // fp32 final edge_out
__device__ float g_logits[N_EDGES];
__device__ float g_scores[N_EDGES];

// ---------------- fp16 helpers ----------------
__device__ __forceinline__ uint2 f4_to_h4(float4 v) {
    __half2 a = __floats2half2_rn(v.x, v.y);
    __half2 b = __floats2half2_rn(v.z, v.w);
    uint2 r;
    r.x = *(unsigned*)&a;
    r.y = *(unsigned*)&b;
    return r;
}
__device__ __forceinline__ float4 h4_to_f4(uint2 v) {
    float2 a = __half22float2(*(__half2*)&v.x);
    float2 b = __half22float2(*(__half2*)&v.y);
    return make_float4(a.x, a.y, b.x, b.y);
}
__device__ __forceinline__ __half2 u2h(unsigned u) { return *(__half2*)&u; }

// ---------------- init: x0 -> fp16 x, zero counters ----------------
__global__ void init_kernel(const float4* __restrict__ x0) {
    int i = blockIdx.x * blockDim.x + threadIdx.x;
    int stride = gridDim.x * blockDim.x;
    for (int k = i; k < N_NODES * 32; k += stride) g_x[k] = f4_to_h4(x0[k]);
    for (int k = i; k < N_EDGES; k += stride) g_edge_cnt[k] = 0;
    for (int k = i; k < N_NODES; k += stride) g_node_cnt[k] = 0;
}

// ---------------- single pass over dense H: build adjacency ----------------
__global__ void build_kernel(const float* __restrict__ H) {
    const long long total4 = (long long)N_NODES * N_EDGES / 4;
    long long idx = (long long)blockIdx.x * blockDim.x + threadIdx.x;
    long long stride = (long long)gridDim.x * blockDim.x;
    const float4* H4 = (const float4*)H;
    for (long long q = idx; q < total4; q += stride) {
        float4 v = __ldg(&H4[q]);
        long long l = q * 4;
        int n = (int)(l / N_EDGES);
        int e = (int)(l % N_EDGES);
        float vals[4] = {v.x, v.y, v.z, v.w};
        #pragma unroll
        for (int c = 0; c < 4; c++) {
            if (vals[c] != 0.0f) {
                int ee = e + c;
                int pe = atomicAdd(&g_edge_cnt[ee], 1);
                if (pe < ECAP) g_edge_nodes[ee * ECAP + pe] = n;
                int pn = atomicAdd(&g_node_cnt[n], 1);
                if (pn < NCAP) g_node_edges[n * NCAP + pn] = ee;
            }
        }
    }
}

// ---------------- degree inverses ----------------
__global__ void inv_kernel() {
    int i = blockIdx.x * blockDim.x + threadIdx.x;
    if (i < N_EDGES) g_de_inv[i] = 1.0f / fmaxf((float)g_edge_cnt[i], DEG_EPS);
    if (i < N_NODES) g_dv_inv[i] = 1.0f / fmaxf((float)g_node_cnt[i], DEG_EPS);
}

// ---------------- V -> E mean: 4 warps per edge, fp16 gather ----------------
// FINAL=false: half2 accumulate, write fp16 g_edge_h.
// FINAL=true : fp32 accumulate, write fp32 g_edge_out.
template <bool FINAL>
__global__ void v2e_kernel() {
    int e = blockIdx.x;                 // block = 1 edge, 128 threads
    int w = threadIdx.x >> 5;
    int lane = threadIdx.x & 31;
    __shared__ float4 part[4][32];

    int deg = min(g_edge_cnt[e], ECAP);
    const int* lst = &g_edge_nodes[e * ECAP];
    int q = (deg + 3) >> 2;
    int start = w * q;
    int end = min(start + q, deg);

    float4 fs = make_float4(0.f, 0.f, 0.f, 0.f);
    __half2 z = __floats2half2_rn(0.f, 0.f);
    __half2 a0x = z, a0y = z, a1x = z, a1y = z, a2x = z, a2y = z, a3x = z, a3y = z;

    for (int base = start; base < end; base += 32) {
        int m = min(32, end - base);
        int idx = lst[base + min(lane, m - 1)];
        int k = 0;
        for (; k + 4 <= m; k += 4) {
            int n0 = __shfl_sync(FULL, idx, k);
            int n1 = __shfl_sync(FULL, idx, k + 1);
            int n2 = __shfl_sync(FULL, idx, k + 2);
            int n3 = __shfl_sync(FULL, idx, k + 3);
            uint2 v0 = g_x[n0 * 32 + lane];
            uint2 v1 = g_x[n1 * 32 + lane];
            uint2 v2 = g_x[n2 * 32 + lane];
            uint2 v3 = g_x[n3 * 32 + lane];
            if (FINAL) {
                float4 f0 = h4_to_f4(v0), f1 = h4_to_f4(v1);
                float4 f2 = h4_to_f4(v2), f3 = h4_to_f4(v3);
                fs.x += (f0.x + f1.x) + (f2.x + f3.x);
                fs.y += (f0.y + f1.y) + (f2.y + f3.y);
                fs.z += (f0.z + f1.z) + (f2.z + f3.z);
                fs.w += (f0.w + f1.w) + (f2.w + f3.w);
            } else {
                a0x = __hadd2(a0x, u2h(v0.x)); a0y = __hadd2(a0y, u2h(v0.y));
                a1x = __hadd2(a1x, u2h(v1.x)); a1y = __hadd2(a1y, u2h(v1.y));
                a2x = __hadd2(a2x, u2h(v2.x)); a2y = __hadd2(a2y, u2h(v2.y));
                a3x = __hadd2(a3x, u2h(v3.x)); a3y = __hadd2(a3y, u2h(v3.y));
            }
        }
        for (; k < m; k++) {
            int n0 = __shfl_sync(FULL, idx, k);
            uint2 v0 = g_x[n0 * 32 + lane];
            if (FINAL) {
                float4 f0 = h4_to_f4(v0);
                fs.x += f0.x; fs.y += f0.y; fs.z += f0.z; fs.w += f0.w;
            } else {
                a0x = __hadd2(a0x, u2h(v0.x)); a0y = __hadd2(a0y, u2h(v0.y));
            }
        }
    }

    float4 p;
    if (FINAL) {
        p = fs;
    } else {
        float2 sx0 = __half22float2(a0x), sx1 = __half22float2(a1x);
        float2 sx2 = __half22float2(a2x), sx3 = __half22float2(a3x);
        float2 sy0 = __half22float2(a0y), sy1 = __half22float2(a1y);
        float2 sy2 = __half22float2(a2y), sy3 = __half22float2(a3y);
        p.x = (sx0.x + sx1.x) + (sx2.x + sx3.x);
        p.y = (sx0.y + sx1.y) + (sx2.y + sx3.y);
        p.z = (sy0.x + sy1.x) + (sy2.x + sy3.x);
        p.w = (sy0.y + sy1.y) + (sy2.y + sy3.y);
    }
    part[w][lane] = p;
    __syncthreads();
    if (w == 0) {
        float4 p0 = part[0][lane], p1 = part[1][lane], p2 = part[2][lane], p3 = part[3][lane];
        float s = g_de_inv[e];
        float4 r;
        r.x = ((p0.x + p1.x) + (p2.x + p3.x)) * s;
        r.y = ((p0.y + p1.y) + (p2.y + p3.y)) * s;
        r.z = ((p0.z + p1.z) + (p2.z + p3.z)) * s;
        r.w = ((p0.w + p1.w) + (p2.w + p3.w)) * s;
        if (FINAL) g_edge_out[e * 32 + lane] = r;
        else       g_edge_h[e * 32 + lane] = f4_to_h4(r);
    }
}

// ---------------- E -> V mean + residual + LayerNorm: one warp per node ----------------
__global__ void e2v_ln_kernel(const float4* __restrict__ x0,
                              const float4* __restrict__ gamma,
                              const float4* __restrict__ beta) {
    int n = (blockIdx.x * blockDim.x + threadIdx.x) >> 5;
    int lane = threadIdx.x & 31;
    int deg = min(g_node_cnt[n], NCAP);
    const int* lst = &g_node_edges[n * NCAP];

    __half2 z = __floats2half2_rn(0.f, 0.f);
    __half2 a0x = z, a0y = z, a1x = z, a1y = z, a2x = z, a2y = z, a3x = z, a3y = z;

    for (int base = 0; base < deg; base += 32) {
        int m = min(32, deg - base);
        int idx = lst[base + min(lane, m - 1)];
        int k = 0;
        for (; k + 4 <= m; k += 4) {
            int e0 = __shfl_sync(FULL, idx, k);
            int e1 = __shfl_sync(FULL, idx, k + 1);
            int e2 = __shfl_sync(FULL, idx, k + 2);
            int e3 = __shfl_sync(FULL, idx, k + 3);
            uint2 v0 = g_edge_h[e0 * 32 + lane];
            uint2 v1 = g_edge_h[e1 * 32 + lane];
            uint2 v2 = g_edge_h[e2 * 32 + lane];
            uint2 v3 = g_edge_h[e3 * 32 + lane];
            a0x = __hadd2(a0x, u2h(v0.x)); a0y = __hadd2(a0y, u2h(v0.y));
            a1x = __hadd2(a1x, u2h(v1.x)); a1y = __hadd2(a1y, u2h(v1.y));
            a2x = __hadd2(a2x, u2h(v2.x)); a2y = __hadd2(a2y, u2h(v2.y));
            a3x = __hadd2(a3x, u2h(v3.x)); a3y = __hadd2(a3y, u2h(v3.y));
        }
        for (; k < m; k++) {
            int e0 = __shfl_sync(FULL, idx, k);
            uint2 v0 = g_edge_h[e0 * 32 + lane];
            a0x = __hadd2(a0x, u2h(v0.x)); a0y = __hadd2(a0y, u2h(v0.y));
        }
    }

    float2 sx0 = __half22float2(a0x), sx1 = __half22float2(a1x);
    float2 sx2 = __half22float2(a2x), sx3 = __half22float2(a3x);
    float2 sy0 = __half22float2(a0y), sy1 = __half22float2(a1y);
    float2 sy2 = __half22float2(a2y), sy3 = __half22float2(a3y);
    float s = g_dv_inv[n];
    float4 r = x0[n * 32 + lane];
    float4 y;
    y.x = ((sx0.x + sx1.x) + (sx2.x + sx3.x)) * s + r.x;
    y.y = ((sx0.y + sx1.y) + (sx2.y + sx3.y)) * s + r.y;
    y.z = ((sy0.x + sy1.x) + (sy2.x + sy3.x)) * s + r.z;
    y.w = ((sy0.y + sy1.y) + (sy2.y + sy3.y)) * s + r.w;

    float sm = (y.x + y.y) + (y.z + y.w);
    #pragma unroll
    for (int o = 16; o > 0; o >>= 1) sm += __shfl_xor_sync(FULL, sm, o);
    float mu = sm * (1.0f / D);
    float4 dy;
    dy.x = y.x - mu; dy.y = y.y - mu; dy.z = y.z - mu; dy.w = y.w - mu;
    float s2 = (dy.x * dy.x + dy.y * dy.y) + (dy.z * dy.z + dy.w * dy.w);
    #pragma unroll
    for (int o = 16; o > 0; o >>= 1) s2 += __shfl_xor_sync(FULL, s2, o);
    float rstd = rsqrtf(s2 * (1.0f / D) + LN_EPS);
    float4 g = gamma[lane];
    float4 bb = beta[lane];
    float4 o4;
    o4.x = dy.x * rstd * g.x + bb.x;
    o4.y = dy.y * rstd * g.y + bb.y;
    o4.z = dy.z * rstd * g.z + bb.z;
    o4.w = dy.w * rstd * g.w + bb.w;
    g_x[n * 32 + lane] = f4_to_h4(o4);
}

// ---------------- attention logits: one warp per edge (fp32 edge_out) ----------------
__global__ void logits_kernel(const float* __restrict__ W,
                              const float* __restrict__ b,
                              const float* __restrict__ q) {
    int e = (blockIdx.x * blockDim.x + threadIdx.x) >> 5;
    int j = threadIdx.x & 31;
    if (e >= N_EDGES) return;
    const float* eo = (const float*)&g_edge_out[e * 32];
    float acc = 0.0f;
    #pragma unroll 4
    for (int dd = 0; dd < D; dd++) acc += eo[dd] * W[dd * ATT + j];
    float t = tanhf(acc + b[j]) * q[j];
    #pragma unroll
    for (int o = 16; o > 0; o >>= 1) t += __shfl_xor_sync(FULL, t, o);
    if (j == 0) g_logits[e] = t;
}

// ---------------- softmax over E (single block) ----------------
__global__ void softmax_kernel() {
    __shared__ float red[32];
    int t = threadIdx.x;
    float m = -1e30f;
    for (int e = t; e < N_EDGES; e += blockDim.x) m = fmaxf(m, g_logits[e]);
    #pragma unroll
    for (int o = 16; o > 0; o >>= 1) m = fmaxf(m, __shfl_xor_sync(FULL, m, o));
    if ((t & 31) == 0) red[t >> 5] = m;
    __syncthreads();
    if (t < 32) {
        float v = red[t];
        #pragma unroll
        for (int o = 16; o > 0; o >>= 1) v = fmaxf(v, __shfl_xor_sync(FULL, v, o));
        if (t == 0) red[0] = v;
    }
    __syncthreads();
    float mx = red[0];
    __syncthreads();
    float s = 0.0f;
    for (int e = t; e < N_EDGES; e += blockDim.x) s += expf(g_logits[e] - mx);
    #pragma unroll
    for (int o = 16; o > 0; o >>= 1) s += __shfl_xor_sync(FULL, s, o);
    if ((t & 31) == 0) red[t >> 5] = s;
    __syncthreads();
    if (t < 32) {
        float v = red[t];
        #pragma unroll
        for (int o = 16; o > 0; o >>= 1) v += __shfl_xor_sync(FULL, v, o);
        if (t == 0) red[0] = v;
    }
    __syncthreads();
    float inv = 1.0f / red[0];
    for (int e = t; e < N_EDGES; e += blockDim.x)
        g_scores[e] = expf(g_logits[e] - mx) * inv;
}

// ---------------- pooled output ----------------
__global__ void pool_kernel(float* __restrict__ out) {
    int d = blockIdx.x;
    int t = threadIdx.x;
    const float* eo = (const float*)g_edge_out;
    float acc = 0.0f;
    for (int e = t; e < N_EDGES; e += blockDim.x)
        acc += g_scores[e] * eo[e * D + d];
    __shared__ float red[8];
    #pragma unroll
    for (int o = 16; o > 0; o >>= 1) acc += __shfl_xor_sync(FULL, acc, o);
    if ((t & 31) == 0) red[t >> 5] = acc;
    __syncthreads();
    if (t == 0) {
        float s = 0.0f;
        for (int w = 0; w < (blockDim.x >> 5); w++) s += red[w];
        out[d] = s;
    }
}

// ---------------- launch ----------------
extern "C" void kernel_launch(void* const* d_in, const int* in_sizes, int n_in,
                              void* d_out, int out_size) {
    const float* x0    = (const float*)d_in[0];   // node_embeddings [N, D]
    const float* H     = (const float*)d_in[1];   // hypergraph_matrix [N, E]
    const float* gamma = (const float*)d_in[2];   // ln_gamma [D]
    const float* beta  = (const float*)d_in[3];   // ln_beta [D]
    const float* W     = (const float*)d_in[4];   // W_att [D, ATT]
    const float* b     = (const float*)d_in[5];   // b_att [ATT]
    const float* q     = (const float*)d_in[6];   // q_att [ATT]
    float* out = (float*)d_out;

    init_kernel<<<2048, 256>>>((const float4*)x0);
    build_kernel<<<4096, 256>>>(H);
    inv_kernel<<<(N_NODES + 255) / 256, 256>>>();

    for (int l = 0; l < 4; l++) {
        v2e_kernel<false><<<N_EDGES, 128>>>();                    // 4 warps / edge
        e2v_ln_kernel<<<N_NODES / 8, 256>>>((const float4*)x0,
                                            (const float4*)gamma,
                                            (const float4*)beta); // 1 warp / node
    }
    // final per-edge masked mean (fp32 accumulate + fp32 output)
    v2e_kernel<true><<<N_EDGES, 128>>>();

    logits_kernel<<<(N_EDGES + 7) / 8, 256>>>(W, b, q);
    softmax_kernel<<<1, 1024>>>();
    pool_kernel<<<D, 256>>>(out);
}